// round 1
// baseline (speedup 1.0000x reference)
#include <cuda_runtime.h>
#include <stdint.h>

// Problem constants
#define Dq   64      // embedding dim
#define KTOT 1024    // num embeddings
#define KC   64      // codebook chunk rows held in smem
#define TM   64      // vectors (w positions) per block
#define Bn   16
#define Hn   64
#define Wn   64
#define HW   (Hn*Wn)
#define QELEMS (Bn*Dq*Hn*Wn)   // 4194304

__device__ float g_cnorm[KTOT];

// Precompute ||c_k||^2 with per-product rounding (mul then add, sequential
// ascending d) to mimic jnp.sum(codebook**2, axis=1). Also zero the loss slot.
__global__ void vq_cnorm_kernel(const float* __restrict__ cb, float* __restrict__ loss_ptr) {
    int k = blockIdx.x * blockDim.x + threadIdx.x;
    if (k == 0 && blockIdx.x == 0) *loss_ptr = 0.0f;
    if (k < KTOT) {
        float s = 0.0f;
        #pragma unroll
        for (int d = 0; d < Dq; ++d) {
            float c = cb[(size_t)k * Dq + d];
            s = __fadd_rn(s, __fmul_rn(c, c));
        }
        g_cnorm[k] = s;
    }
}

__global__ __launch_bounds__(256) void vq_main_kernel(
    const float* __restrict__ x,
    const float* __restrict__ cb,
    float* __restrict__ out,
    float* __restrict__ loss_ptr)
{
    __shared__ __align__(16) float xs[Dq][TM];   // xs[d][w]
    __shared__ float cs[KC][Dq];                 // cs[k][d] (chunk)
    __shared__ float cn_s[KC];
    __shared__ float sxn[TM];
    __shared__ unsigned long long red[TM][16];
    __shared__ int sidx[TM];
    __shared__ float lred[256];

    const int bid = blockIdx.x;          // b*Hn + h
    const int b = bid >> 6;
    const int h = bid & 63;
    const int tid = threadIdx.x;

    const float* xblk = x + (size_t)b * Dq * HW + (size_t)h * Wn;   // x[b,d,h,w] = xblk[d*HW + w]

    // ---- load x tile (coalesced: w contiguous per instruction) ----
    {
        int w  = tid & 63;
        int d0 = tid >> 6;       // 0..3
        #pragma unroll
        for (int i = 0; i < 16; ++i) {
            int d = d0 + 4 * i;
            xs[d][w] = xblk[(size_t)d * HW + w];
        }
    }
    __syncthreads();

    // ---- ||x||^2 per w: per-product rounding, sequential ascending d ----
    if (tid < TM) {
        float s = 0.0f;
        #pragma unroll
        for (int d = 0; d < Dq; ++d) {
            float v = xs[d][tid];
            s = __fadd_rn(s, __fmul_rn(v, v));
        }
        sxn[tid] = s;
    }
    __syncthreads();

    const int tw = tid & 15;     // w-group: handles w = tw*4 .. tw*4+3
    const int tk = tid >> 4;     // k-group: handles k = tk*4 .. tk*4+3 (per chunk)

    const float INF = __int_as_float(0x7f800000);
    float runmin[4] = {INF, INF, INF, INF};
    int   runidx[4] = {0, 0, 0, 0};
    float xnw[4];
    #pragma unroll
    for (int j = 0; j < 4; ++j) xnw[j] = sxn[tw * 4 + j];

    for (int kc = 0; kc < KTOT / KC; ++kc) {
        // ---- load codebook chunk (coalesced read, conflict-free store) ----
        {
            int d   = tid & 63;
            int kk0 = tid >> 6;
            #pragma unroll
            for (int i = 0; i < 16; ++i) {
                int kk = kk0 + 4 * i;
                cs[kk][d] = cb[(size_t)(kc * KC + kk) * Dq + d];
            }
            if (tid < KC) cn_s[tid] = g_cnorm[kc * KC + tid];
        }
        __syncthreads();

        // ---- 4x4 register tile GEMM over d (sequential ascending FMA per acc) ----
        float acc[4][4];
        #pragma unroll
        for (int a = 0; a < 4; ++a)
            #pragma unroll
            for (int c2 = 0; c2 < 4; ++c2) acc[a][c2] = 0.0f;

        #pragma unroll 8
        for (int d = 0; d < Dq; ++d) {
            const float4 xv = *reinterpret_cast<const float4*>(&xs[d][tw << 2]);
            float xr[4] = {xv.x, xv.y, xv.z, xv.w};
            #pragma unroll
            for (int jk = 0; jk < 4; ++jk) {
                float c = cs[(tk << 2) + jk][d];
                #pragma unroll
                for (int jw = 0; jw < 4; ++jw)
                    acc[jw][jk] = fmaf(xr[jw], c, acc[jw][jk]);
            }
        }

        // ---- scores, mimic reference rounding: fl(fl(xn+cn) - fl(2*dot)) ----
        #pragma unroll
        for (int jk = 0; jk < 4; ++jk) {
            int k = kc * KC + (tk << 2) + jk;
            float cn = cn_s[(tk << 2) + jk];
            #pragma unroll
            for (int jw = 0; jw < 4; ++jw) {
                float t = __fadd_rn(xnw[jw], cn);
                float s = __fsub_rn(t, __fmul_rn(2.0f, acc[jw][jk]));
                if (s < runmin[jw]) { runmin[jw] = s; runidx[jw] = k; }
            }
        }
        __syncthreads();   // protect cs before next chunk overwrite
    }

    // ---- cross-thread argmin reduce (packed: orderable-float | index) ----
    #pragma unroll
    for (int jw = 0; jw < 4; ++jw) {
        unsigned u = __float_as_uint(runmin[jw]);
        u = (u & 0x80000000u) ? ~u : (u | 0x80000000u);
        red[(tw << 2) + jw][tk] = ((unsigned long long)u << 32) | (unsigned)runidx[jw];
    }
    __syncthreads();
    if (tid < TM) {
        unsigned long long m = red[tid][0];
        #pragma unroll
        for (int i = 1; i < 16; ++i) {
            unsigned long long v = red[tid][i];
            if (v < m) m = v;
        }
        sidx[tid] = (int)(m & 0xFFFFFFFFull);
    }
    __syncthreads();

    // ---- gather + straight-through output + loss accumulation ----
    float lsum = 0.0f;
    {
        int w  = tid & 63;
        int d0 = tid >> 6;
        int k  = sidx[w];
        const float* crow = cb + (size_t)k * Dq;
        float* oblk = out + (size_t)b * Dq * HW + (size_t)h * Wn;
        #pragma unroll
        for (int i = 0; i < 16; ++i) {
            int d = d0 + 4 * i;
            float q  = __ldg(&crow[d]);
            float xv = xs[d][w];
            float diff = __fsub_rn(q, xv);                       // fl(q - x)
            lsum = __fadd_rn(lsum, __fmul_rn(diff, diff));
            oblk[(size_t)d * HW + w] = __fadd_rn(xv, diff);      // fl(x + fl(q-x))
        }
    }
    lred[tid] = lsum;
    __syncthreads();
    #pragma unroll
    for (int s2 = 128; s2 > 0; s2 >>= 1) {
        if (tid < s2) lred[tid] = __fadd_rn(lred[tid], lred[tid + s2]);
        __syncthreads();
    }
    if (tid == 0) {
        // loss = (1 + COMMITMENT_COST) * mean(diff^2); scale before atomic add
        atomicAdd(loss_ptr, lred[0] * (1.25f / (float)QELEMS));
    }
}

extern "C" void kernel_launch(void* const* d_in, const int* in_sizes, int n_in,
                              void* d_out, int out_size) {
    const float* x  = (const float*)d_in[0];
    const float* cb = (const float*)d_in[1];
    float* out = (float*)d_out;
    float* loss_ptr = out + (out_size - 1);   // outputs: [quantized (4194304), loss (1)]

    vq_cnorm_kernel<<<4, 256>>>(cb, loss_ptr);
    vq_main_kernel<<<Bn * Hn, 256>>>(x, cb, out, loss_ptr);
}